// round 9
// baseline (speedup 1.0000x reference)
#include <cuda_runtime.h>
#include <cstdint>

// Problem constants
#define B_       128
#define T_IN     240
#define T_OUT    30
#define D_       128
#define H_       256
#define G3       768              // 3*H
#define STRIDE_  8
#define ENC_STEPS (T_IN * B_)     // 30720
#define DEC_STEPS (T_OUT * B_)    // 3840

// Scratch: precomputed input projections gi = x @ Wih^T + b_ih
__device__ float GI_enc[ENC_STEPS * G3];   // ~94.4 MB
__device__ float GI_dec[DEC_STEPS * G3];   // ~11.8 MB

// ---------------------------------------------------------------------------
// Kernel 1: GI GEMM.  GI[s][row] = b_ih[row] + sum_d X[s,d] * Wih[row][d]
// ---------------------------------------------------------------------------
#define S_TILE     32
#define ENC_BLOCKS (ENC_STEPS / S_TILE)   // 960
#define DEC_BLOCKS (DEC_STEPS / S_TILE)   // 120

__global__ void __launch_bounds__(768, 1) gi_kernel(
    const float* __restrict__ x,
    const float* __restrict__ Wih_e, const float* __restrict__ bih_e,
    const float* __restrict__ Wih_d, const float* __restrict__ bih_d)
{
    __shared__ __align__(16) float Xs[S_TILE][D_];   // 16 KB

    bool enc = blockIdx.x < ENC_BLOCKS;
    int  sblk = enc ? blockIdx.x : blockIdx.x - ENC_BLOCKS;
    int  s0   = sblk * S_TILE;
    const float* W   = enc ? Wih_e : Wih_d;
    const float* bih = enc ? bih_e : bih_d;
    float*       GI  = enc ? GI_enc : GI_dec;
    int tstride = enc ? 1 : STRIDE_;

    int tid = threadIdx.x;

    for (int idx = tid; idx < S_TILE * D_; idx += 768) {
        int i = idx >> 7;
        int k = idx & 127;
        int s = s0 + i;
        int b = s & 127;
        int t = (s >> 7) * tstride;
        Xs[i][k] = x[(size_t)b * (T_IN * D_) + (size_t)t * D_ + k];
    }
    __syncthreads();

    int row = tid;
    const float4* W4 = (const float4*)(W + (size_t)row * D_);

    float acc[S_TILE];
#pragma unroll
    for (int i = 0; i < S_TILE; i++) acc[i] = 0.f;

#pragma unroll 4
    for (int kk = 0; kk < D_ / 4; kk++) {
        float4 w = W4[kk];
#pragma unroll
        for (int i = 0; i < S_TILE; i++) {
            float4 xv = ((const float4*)Xs[i])[kk];
            acc[i] += w.x * xv.x + w.y * xv.y + w.z * xv.z + w.w * xv.w;
        }
    }

    float bv = bih[row];
#pragma unroll
    for (int i = 0; i < S_TILE; i++)
        GI[(size_t)(s0 + i) * G3 + row] = acc[i] + bv;
}

// ---------------------------------------------------------------------------
// Kernel 2: serial GRU scans.  8-CTA cluster, register-resident W_hh.
// Cross-CTA h exchange via cp.async.bulk.shared::cluster.shared::cta:
// each producer stages its 32 hnew values in SMEM (128 B) and issues ONE
// bulk copy per consumer CTA, delivering ONE complete_tx(128B) per producer
// at the consumer's mbarrier (8 tx updates/step instead of 128 st.async).
// Two ping-pong mbarriers; expect_tx(1024) per step.  128 threads/CTA.
//
// Thread layout (unchanged from R6):
//   warp w (0..3), lane: o = lane>>3 (column slice 0..3, 64 cols each),
//   jq = lane&7, jloc = w*8 + jq, j = crank*32 + jloc.
// Each thread: rows {j, 256+j, 512+j} x cols [o*64, o*64+64) = 192 weights.
// Reduce: 2-round shfl butterfly (xor 8, 16); gates redundant per lane;
// hold carried in register.
// ---------------------------------------------------------------------------
#define CLUSTER  8
#define NTHREADS 128
#define TX_BYTES (H_ * 4)        // 1024 = 8 producers x 128 B
#define STAGE_BYTES (32 * 4)     // 128 B per producer per step

__device__ __forceinline__ uint32_t smem_u32(const void* p) {
    return (uint32_t)__cvta_generic_to_shared(p);
}
__device__ __forceinline__ uint32_t mapa_shared(uint32_t addr, uint32_t rank) {
    uint32_t r;
    asm volatile("mapa.shared::cluster.u32 %0, %1, %2;" : "=r"(r) : "r"(addr), "r"(rank));
    return r;
}
__device__ __forceinline__ void mbar_init_(uint32_t addr, uint32_t count) {
    asm volatile("mbarrier.init.shared.b64 [%0], %1;" :: "r"(addr), "r"(count) : "memory");
}
__device__ __forceinline__ void mbar_arm_(uint32_t addr, uint32_t tx) {
    asm volatile("mbarrier.arrive.expect_tx.shared.b64 _, [%0], %1;"
                 :: "r"(addr), "r"(tx) : "memory");
}
__device__ __forceinline__ void mbar_wait_(uint32_t addr, uint32_t parity) {
    asm volatile(
        "{\n\t"
        ".reg .pred P;\n\t"
        "W_%=:\n\t"
        "mbarrier.try_wait.parity.shared.b64 P, [%0], %1, 0x989680;\n\t"
        "@!P bra W_%=;\n\t"
        "}"
        :: "r"(addr), "r"(parity) : "memory");
}
__device__ __forceinline__ void bulk_s2s_cluster_(uint32_t dst_cluster,
                                                  uint32_t src_cta,
                                                  uint32_t nbytes,
                                                  uint32_t mbar_cluster) {
    asm volatile(
        "cp.async.bulk.shared::cluster.shared::cta.mbarrier::complete_tx::bytes "
        "[%0], [%1], %2, [%3];"
        :: "r"(dst_cluster), "r"(src_cta), "r"(nbytes), "r"(mbar_cluster) : "memory");
}
__device__ __forceinline__ void fence_proxy_async_() {
    asm volatile("fence.proxy.async.shared::cta;" ::: "memory");
}
__device__ __forceinline__ void cluster_arrive_() {
    asm volatile("barrier.cluster.arrive.aligned;" ::: "memory");
}
__device__ __forceinline__ void cluster_wait_() {
    asm volatile("barrier.cluster.wait.aligned;" ::: "memory");
}
__device__ __forceinline__ void fma2_(unsigned long long& acc,
                                      unsigned long long a, unsigned long long b) {
    asm("fma.rn.f32x2 %0, %1, %2, %0;" : "+l"(acc) : "l"(a), "l"(b));
}
__device__ __forceinline__ float hsum2_(unsigned long long v) {
    float lo, hi;
    asm("mov.b64 {%0, %1}, %2;" : "=f"(lo), "=f"(hi) : "l"(v));
    return lo + hi;
}
__device__ __forceinline__ float sigmoid_(float xv) {
    return __fdividef(1.0f, 1.0f + __expf(-xv));
}
__device__ __forceinline__ float tanh_(float xv) {
    return 1.0f - __fdividef(2.0f, __expf(2.0f * xv) + 1.0f);
}

__global__ void __launch_bounds__(NTHREADS, 1) scan_kernel(
    const float* __restrict__ Whh_e, const float* __restrict__ bhh_e,
    const float* __restrict__ Whh_d, const float* __restrict__ bhh_d,
    float* __restrict__ out)
{
    __shared__ __align__(16) float hbuf[2][H_];
    __shared__ __align__(16) float stage[2][32];        // outgoing hnew, x2 buffered
    __shared__ __align__(8) unsigned long long mb[2];   // mb[b] guards hbuf[b]

    bool enc = (blockIdx.x >> 3) == 0;
    uint32_t crank;
    asm("mov.u32 %0, %%cluster_ctarank;" : "=r"(crank));

    const float* Whh = enc ? Whh_e : Whh_d;
    const float* bhh = enc ? bhh_e : bhh_d;
    const float* GI  = enc ? GI_enc : GI_dec;
    int    nsteps = enc ? ENC_STEPS : DEC_STEPS;
    float* outp   = enc ? out : (out + 240 * H_);

    int tid  = threadIdx.x;
    int w    = tid >> 5;
    int lane = tid & 31;
    int o    = lane >> 3;             // column slice (0..3): cols [o*64, o*64+64)
    int jq   = lane & 7;
    int jloc = w * 8 + jq;            // local output index 0..31
    int j    = (int)crank * 32 + jloc;

    // ---- load this thread's 192 weights as 96 packed f32x2 ----
    unsigned long long wr_[32], wz_[32], wn_[32];
    {
        const ulonglong2* Pr = (const ulonglong2*)(Whh + (size_t)j * H_ + o * 64);
        const ulonglong2* Pz = (const ulonglong2*)(Whh + (size_t)(256 + j) * H_ + o * 64);
        const ulonglong2* Pn = (const ulonglong2*)(Whh + (size_t)(512 + j) * H_ + o * 64);
#pragma unroll
        for (int k = 0; k < 16; k++) {
            ulonglong2 vr = Pr[k]; wr_[2*k] = vr.x; wr_[2*k+1] = vr.y;
            ulonglong2 vz = Pz[k]; wz_[2*k] = vz.x; wz_[2*k+1] = vz.y;
            ulonglong2 vn = Pn[k]; wn_[2*k] = vn.x; wn_[2*k+1] = vn.y;
        }
    }

    float bh_r = bhh[j];
    float bh_z = bhh[256 + j];
    float bh_n = bhh[512 + j];

    // bulk-copy addressing: thread t (<8) serves consumer CTA rank t.
    // dst = consumer's hbuf[b][crank*32] (this producer's 32-float slot),
    // mbar = consumer's mb[b].
    uint32_t dstH[2] = {0, 0}, dstMB[2] = {0, 0};
    if (tid < CLUSTER) {
        dstH[0]  = mapa_shared(smem_u32(&hbuf[0][(int)crank * 32]), (uint32_t)tid);
        dstH[1]  = mapa_shared(smem_u32(&hbuf[1][(int)crank * 32]), (uint32_t)tid);
        dstMB[0] = mapa_shared(smem_u32(&mb[0]), (uint32_t)tid);
        dstMB[1] = mapa_shared(smem_u32(&mb[1]), (uint32_t)tid);
    }
    uint32_t srcStage[2] = { smem_u32(&stage[0][0]), smem_u32(&stage[1][0]) };
    uint32_t locMB[2]    = { smem_u32(&mb[0]), smem_u32(&mb[1]) };

    // init: h0 = 0; barriers init (count=1) and pre-armed for first use
    hbuf[0][tid] = 0.f;
    hbuf[0][tid + 128] = 0.f;
    if (tid == 0) {
        mbar_init_(locMB[0], 1);
        mbar_init_(locMB[1], 1);
        mbar_arm_(locMB[0], TX_BYTES);   // first use: step 2 (h(1))
        mbar_arm_(locMB[1], TX_BYTES);   // first use: step 1 (h(0))
    }
    __syncthreads();
    cluster_arrive_();     // barrier inits visible before any remote bulk copy
    cluster_wait_();

    // gi prefetch ring, distance 2
    float g0r = __ldg(&GI[j]);
    float g0z = __ldg(&GI[256 + j]);
    float g0n = __ldg(&GI[512 + j]);
    float g1r = 0.f, g1z = 0.f, g1n = 0.f;
    if (nsteps > 1) {
        const float* g = GI + (size_t)G3;
        g1r = __ldg(&g[j]);
        g1z = __ldg(&g[256 + j]);
        g1n = __ldg(&g[512 + j]);
    }

    uint32_t par0 = 0, par1 = 0;   // per-barrier phase parity
    float hold = 0.f;              // h[j], carried in register

    for (int s = 0; s < nsteps; s++) {
        int rd  = s & 1;          // h(s-1) lives in hbuf[rd], guarded by mb[rd]
        int wrb = rd ^ 1;         // h(s) goes to hbuf[wrb] / mb[wrb]

        // issue gi prefetch for s+2 BEFORE the wait (hides DRAM latency)
        float nr = 0.f, nz = 0.f, nn = 0.f;
        if ((s + 2) < nsteps) {
            const float* g = GI + (size_t)(s + 2) * G3;
            nr = __ldg(&g[j]);
            nz = __ldg(&g[256 + j]);
            nn = __ldg(&g[512 + j]);
        }

        if (s > 0) {
            if (rd) { mbar_wait_(locMB[1], par1); par1 ^= 1; }
            else    { mbar_wait_(locMB[0], par0); par0 ^= 1; }
            // re-arm this barrier for its next use (step s+2), new phase
            if (tid == 0) mbar_arm_(locMB[rd], TX_BYTES);
        }

        // ---- matvec over this thread's 64-col slice (3 rows) ----
        const ulonglong2* hp = (const ulonglong2*)(&hbuf[rd][o * 64]);
        unsigned long long ar0 = 0ull, ar1 = 0ull;
        unsigned long long az0 = 0ull, az1 = 0ull;
        unsigned long long an0 = 0ull, an1 = 0ull;
#pragma unroll
        for (int k = 0; k < 16; k++) {
            ulonglong2 hv = hp[k];
            fma2_(ar0, wr_[2*k], hv.x); fma2_(ar1, wr_[2*k+1], hv.y);
            fma2_(az0, wz_[2*k], hv.x); fma2_(az1, wz_[2*k+1], hv.y);
            fma2_(an0, wn_[2*k], hv.x); fma2_(an1, wn_[2*k+1], hv.y);
        }
        float pr = hsum2_(ar0) + hsum2_(ar1);
        float pz = hsum2_(az0) + hsum2_(az1);
        float pn = hsum2_(an0) + hsum2_(an1);

        // ---- butterfly reduce over the 4 column slices (lanes xor 8,16)
#pragma unroll
        for (int d = 8; d < 32; d <<= 1) {
            pr += __shfl_xor_sync(0xffffffffu, pr, d);
            pz += __shfl_xor_sync(0xffffffffu, pz, d);
            pn += __shfl_xor_sync(0xffffffffu, pn, d);
        }

        // ---- gates (all 4 lanes of a j redundantly) ----
        float r    = sigmoid_(g0r + pr + bh_r);
        float z    = sigmoid_(g0z + pz + bh_z);
        float n    = tanh_(g0n + r * (pn + bh_n));
        float hnew = n + z * (hold - n);   // (1-z)*n + z*h
        hold = hnew;

        // ---- stage outgoing hnew, then ONE bulk copy per consumer CTA ----
        if (o == 0) stage[wrb][jloc] = hnew;
        __syncthreads();   // all 32 staged values visible CTA-wide
        if ((s + 1) < nsteps && tid < CLUSTER) {
            fence_proxy_async_();   // order STS (generic) before async-proxy read
            bulk_s2s_cluster_(dstH[wrb], srcStage[wrb], STAGE_BYTES, dstMB[wrb]);
        }

        // ---- outputs (lane group o==0 only: unique j per store) ----
        if (o == 0) {
            if (enc) {
                if ((s & 127) == 127)
                    outp[(size_t)(s >> 7) * H_ + j] = hnew;
            } else {
                outp[(size_t)(s & 127) * (T_OUT * H_) + (size_t)(s >> 7) * H_ + j] = hnew;
            }
        }

        // rotate gi ring
        g0r = g1r; g0z = g1z; g0n = g1n;
        g1r = nr;  g1z = nz;  g1n = nn;
    }

    // safety: no CTA exits while peers may still address its SMEM
    cluster_arrive_();
    cluster_wait_();
}

// ---------------------------------------------------------------------------
// Launch
// ---------------------------------------------------------------------------
extern "C" void kernel_launch(void* const* d_in, const int* in_sizes, int n_in,
                              void* d_out, int out_size)
{
    const float* x     = (const float*)d_in[0];
    const float* Wih_e = (const float*)d_in[1];
    const float* Whh_e = (const float*)d_in[2];
    const float* bih_e = (const float*)d_in[3];
    const float* bhh_e = (const float*)d_in[4];
    const float* Wih_d = (const float*)d_in[5];
    const float* Whh_d = (const float*)d_in[6];
    const float* bih_d = (const float*)d_in[7];
    const float* bhh_d = (const float*)d_in[8];
    float* out = (float*)d_out;

    gi_kernel<<<ENC_BLOCKS + DEC_BLOCKS, 768>>>(x, Wih_e, bih_e, Wih_d, bih_d);

    cudaLaunchConfig_t cfg = {};
    cfg.gridDim  = dim3(2 * CLUSTER, 1, 1);
    cfg.blockDim = dim3(NTHREADS, 1, 1);
    cfg.dynamicSmemBytes = 0;
    cfg.stream = 0;
    cudaLaunchAttribute attrs[1];
    attrs[0].id = cudaLaunchAttributeClusterDimension;
    attrs[0].val.clusterDim.x = CLUSTER;
    attrs[0].val.clusterDim.y = 1;
    attrs[0].val.clusterDim.z = 1;
    cfg.attrs = attrs;
    cfg.numAttrs = 1;
    cudaLaunchKernelEx(&cfg, scan_kernel, Whh_e, bhh_e, Whh_d, bhh_d, out);
}

// round 10
// speedup vs baseline: 1.2720x; 1.2720x over previous
#include <cuda_runtime.h>
#include <cstdint>

// Problem constants
#define B_       128
#define T_IN     240
#define T_OUT    30
#define D_       128
#define H_       256
#define G3       768              // 3*H
#define STRIDE_  8
#define ENC_STEPS (T_IN * B_)     // 30720
#define DEC_STEPS (T_OUT * B_)    // 3840

// Scratch: precomputed input projections gi = x @ Wih^T + b_ih
__device__ float GI_enc[ENC_STEPS * G3];   // ~94.4 MB
__device__ float GI_dec[DEC_STEPS * G3];   // ~11.8 MB

// ---------------------------------------------------------------------------
// Kernel 1: GI GEMM.  GI[s][row] = b_ih[row] + sum_d X[s,d] * Wih[row][d]
// ---------------------------------------------------------------------------
#define S_TILE     32
#define ENC_BLOCKS (ENC_STEPS / S_TILE)   // 960
#define DEC_BLOCKS (DEC_STEPS / S_TILE)   // 120

__global__ void __launch_bounds__(768, 1) gi_kernel(
    const float* __restrict__ x,
    const float* __restrict__ Wih_e, const float* __restrict__ bih_e,
    const float* __restrict__ Wih_d, const float* __restrict__ bih_d)
{
    __shared__ __align__(16) float Xs[S_TILE][D_];   // 16 KB

    bool enc = blockIdx.x < ENC_BLOCKS;
    int  sblk = enc ? blockIdx.x : blockIdx.x - ENC_BLOCKS;
    int  s0   = sblk * S_TILE;
    const float* W   = enc ? Wih_e : Wih_d;
    const float* bih = enc ? bih_e : bih_d;
    float*       GI  = enc ? GI_enc : GI_dec;
    int tstride = enc ? 1 : STRIDE_;

    int tid = threadIdx.x;

    for (int idx = tid; idx < S_TILE * D_; idx += 768) {
        int i = idx >> 7;
        int k = idx & 127;
        int s = s0 + i;
        int b = s & 127;
        int t = (s >> 7) * tstride;
        Xs[i][k] = x[(size_t)b * (T_IN * D_) + (size_t)t * D_ + k];
    }
    __syncthreads();

    int row = tid;
    const float4* W4 = (const float4*)(W + (size_t)row * D_);

    float acc[S_TILE];
#pragma unroll
    for (int i = 0; i < S_TILE; i++) acc[i] = 0.f;

#pragma unroll 4
    for (int kk = 0; kk < D_ / 4; kk++) {
        float4 w = W4[kk];
#pragma unroll
        for (int i = 0; i < S_TILE; i++) {
            float4 xv = ((const float4*)Xs[i])[kk];
            acc[i] += w.x * xv.x + w.y * xv.y + w.z * xv.z + w.w * xv.w;
        }
    }

    float bv = bih[row];
#pragma unroll
    for (int i = 0; i < S_TILE; i++)
        GI[(size_t)(s0 + i) * G3 + row] = acc[i] + bv;
}

// ---------------------------------------------------------------------------
// Kernel 2: serial GRU scans.  8-CTA cluster, register-resident W_hh,
// st.async.v4.b32 cross-CTA exchange (16 B per message -> 64 messages per
// consumer per step instead of 128), 2 ping-pong mbarriers, 128 threads/CTA.
//
// Thread layout (same as the 16.3ms R6 kernel):
//   warp w (0..3), lane: o = lane>>3 (column slice 0..3, 64 cols each),
//   jq = lane&7, jloc = w*8 + jq, j = crank*32 + jloc.
// Each thread: rows {j, 256+j, 512+j} x cols [o*64, o*64+64) = 192 weights.
// Reduce: 2-round shfl butterfly (xor 8, 16); gates redundant per lane;
// hold carried in register.
// Send: in-octet gather of the 4-value group via shfl (xor1, xor2); lanes
// with jq%4==0 send ONE v4.b32 (global j group [j&~3, j&~3+4)) to CTA o
// and CTA o+8... (o and o+4 for CLUSTER=8).
// Per consumer per step: 8 producers x 8 groups x 16 B = 1024 tx bytes.
// ---------------------------------------------------------------------------
#define CLUSTER  8
#define NTHREADS 128
#define TX_BYTES (H_ * 4)   // 1024

__device__ __forceinline__ uint32_t smem_u32(const void* p) {
    return (uint32_t)__cvta_generic_to_shared(p);
}
__device__ __forceinline__ uint32_t mapa_shared(uint32_t addr, uint32_t rank) {
    uint32_t r;
    asm volatile("mapa.shared::cluster.u32 %0, %1, %2;" : "=r"(r) : "r"(addr), "r"(rank));
    return r;
}
__device__ __forceinline__ void mbar_init_(uint32_t addr, uint32_t count) {
    asm volatile("mbarrier.init.shared.b64 [%0], %1;" :: "r"(addr), "r"(count) : "memory");
}
__device__ __forceinline__ void mbar_arm_(uint32_t addr, uint32_t tx) {
    asm volatile("mbarrier.arrive.expect_tx.shared.b64 _, [%0], %1;"
                 :: "r"(addr), "r"(tx) : "memory");
}
__device__ __forceinline__ void mbar_wait_(uint32_t addr, uint32_t parity) {
    asm volatile(
        "{\n\t"
        ".reg .pred P;\n\t"
        "W_%=:\n\t"
        "mbarrier.try_wait.parity.shared.b64 P, [%0], %1, 0x989680;\n\t"
        "@!P bra W_%=;\n\t"
        "}"
        :: "r"(addr), "r"(parity) : "memory");
}
__device__ __forceinline__ void st_async_v4(uint32_t remote_addr,
                                            float a, float b, float c, float d,
                                            uint32_t remote_mbar) {
    asm volatile(
        "st.async.shared::cluster.mbarrier::complete_tx::bytes.v4.b32 "
        "[%0], {%1, %2, %3, %4}, [%5];"
        :: "r"(remote_addr),
           "r"(__float_as_uint(a)), "r"(__float_as_uint(b)),
           "r"(__float_as_uint(c)), "r"(__float_as_uint(d)),
           "r"(remote_mbar) : "memory");
}
__device__ __forceinline__ void cluster_arrive_() {
    asm volatile("barrier.cluster.arrive.aligned;" ::: "memory");
}
__device__ __forceinline__ void cluster_wait_() {
    asm volatile("barrier.cluster.wait.aligned;" ::: "memory");
}
__device__ __forceinline__ void fma2_(unsigned long long& acc,
                                      unsigned long long a, unsigned long long b) {
    asm("fma.rn.f32x2 %0, %1, %2, %0;" : "+l"(acc) : "l"(a), "l"(b));
}
__device__ __forceinline__ float hsum2_(unsigned long long v) {
    float lo, hi;
    asm("mov.b64 {%0, %1}, %2;" : "=f"(lo), "=f"(hi) : "l"(v));
    return lo + hi;
}
__device__ __forceinline__ float sigmoid_(float xv) {
    return __fdividef(1.0f, 1.0f + __expf(-xv));
}
__device__ __forceinline__ float tanh_(float xv) {
    return 1.0f - __fdividef(2.0f, __expf(2.0f * xv) + 1.0f);
}

__global__ void __launch_bounds__(NTHREADS, 1) scan_kernel(
    const float* __restrict__ Whh_e, const float* __restrict__ bhh_e,
    const float* __restrict__ Whh_d, const float* __restrict__ bhh_d,
    float* __restrict__ out)
{
    __shared__ __align__(16) float hbuf[2][H_];
    __shared__ __align__(8) unsigned long long mb[2];   // mb[b] guards hbuf[b]

    bool enc = (blockIdx.x >> 3) == 0;
    uint32_t crank;
    asm("mov.u32 %0, %%cluster_ctarank;" : "=r"(crank));

    const float* Whh = enc ? Whh_e : Whh_d;
    const float* bhh = enc ? bhh_e : bhh_d;
    const float* GI  = enc ? GI_enc : GI_dec;
    int    nsteps = enc ? ENC_STEPS : DEC_STEPS;
    float* outp   = enc ? out : (out + 240 * H_);

    int tid  = threadIdx.x;
    int w    = tid >> 5;
    int lane = tid & 31;
    int o    = lane >> 3;             // column slice (0..3): cols [o*64, o*64+64)
    int jq   = lane & 7;
    int jloc = w * 8 + jq;            // local output index 0..31
    int j    = (int)crank * 32 + jloc;

    // ---- load this thread's 192 weights as 96 packed f32x2 ----
    unsigned long long wr_[32], wz_[32], wn_[32];
    {
        const ulonglong2* Pr = (const ulonglong2*)(Whh + (size_t)j * H_ + o * 64);
        const ulonglong2* Pz = (const ulonglong2*)(Whh + (size_t)(256 + j) * H_ + o * 64);
        const ulonglong2* Pn = (const ulonglong2*)(Whh + (size_t)(512 + j) * H_ + o * 64);
#pragma unroll
        for (int k = 0; k < 16; k++) {
            ulonglong2 vr = Pr[k]; wr_[2*k] = vr.x; wr_[2*k+1] = vr.y;
            ulonglong2 vz = Pz[k]; wz_[2*k] = vz.x; wz_[2*k+1] = vz.y;
            ulonglong2 vn = Pn[k]; wn_[2*k] = vn.x; wn_[2*k+1] = vn.y;
        }
    }

    float bh_r = bhh[j];
    float bh_z = bhh[256 + j];
    float bh_n = bhh[512 + j];

    // remote addresses: senders (jq%4==0) send the GLOBAL 4-group [j&~3, +4)
    // as one v4.b32 to CTA o and CTA o+4.  16-B aligned: (j&~3)*4.
    int jgrp = j & ~3;
    uint32_t remH[2][2], remMB[2][2];
    {
        uint32_t a0 = smem_u32(&hbuf[0][jgrp]);
        uint32_t a1 = smem_u32(&hbuf[1][jgrp]);
        uint32_t m0 = smem_u32(&mb[0]);
        uint32_t m1 = smem_u32(&mb[1]);
        remH[0][0]  = mapa_shared(a0, (uint32_t)o);
        remH[0][1]  = mapa_shared(a0, (uint32_t)(o + 4));
        remH[1][0]  = mapa_shared(a1, (uint32_t)o);
        remH[1][1]  = mapa_shared(a1, (uint32_t)(o + 4));
        remMB[0][0] = mapa_shared(m0, (uint32_t)o);
        remMB[0][1] = mapa_shared(m0, (uint32_t)(o + 4));
        remMB[1][0] = mapa_shared(m1, (uint32_t)o);
        remMB[1][1] = mapa_shared(m1, (uint32_t)(o + 4));
    }
    uint32_t locMB[2] = { smem_u32(&mb[0]), smem_u32(&mb[1]) };

    // init: h0 = 0; barriers init (count=1) and pre-armed for first use
    hbuf[0][tid] = 0.f;
    hbuf[0][tid + 128] = 0.f;
    if (tid == 0) {
        mbar_init_(locMB[0], 1);
        mbar_init_(locMB[1], 1);
        mbar_arm_(locMB[0], TX_BYTES);   // first use: step 2 (h(1))
        mbar_arm_(locMB[1], TX_BYTES);   // first use: step 1 (h(0))
    }
    __syncthreads();
    cluster_arrive_();     // barrier inits visible before any remote st.async
    cluster_wait_();

    // gi prefetch ring, distance 2
    float g0r = __ldg(&GI[j]);
    float g0z = __ldg(&GI[256 + j]);
    float g0n = __ldg(&GI[512 + j]);
    float g1r = 0.f, g1z = 0.f, g1n = 0.f;
    if (nsteps > 1) {
        const float* g = GI + (size_t)G3;
        g1r = __ldg(&g[j]);
        g1z = __ldg(&g[256 + j]);
        g1n = __ldg(&g[512 + j]);
    }

    uint32_t par0 = 0, par1 = 0;   // per-barrier phase parity
    float hold = 0.f;              // h[j], carried in register
    bool sender = ((jq & 3) == 0);

    for (int s = 0; s < nsteps; s++) {
        int rd  = s & 1;          // h(s-1) lives in hbuf[rd], guarded by mb[rd]
        int wrb = rd ^ 1;         // h(s) goes to hbuf[wrb] / mb[wrb]

        // issue gi prefetch for s+2 BEFORE the wait (hides DRAM latency)
        float nr = 0.f, nz = 0.f, nn = 0.f;
        if ((s + 2) < nsteps) {
            const float* g = GI + (size_t)(s + 2) * G3;
            nr = __ldg(&g[j]);
            nz = __ldg(&g[256 + j]);
            nn = __ldg(&g[512 + j]);
        }

        if (s > 0) {
            if (rd) { mbar_wait_(locMB[1], par1); par1 ^= 1; }
            else    { mbar_wait_(locMB[0], par0); par0 ^= 1; }
            // re-arm this barrier for its next use (step s+2), new phase
            if (tid == 0) mbar_arm_(locMB[rd], TX_BYTES);
        }

        // ---- matvec over this thread's 64-col slice (3 rows) ----
        const ulonglong2* hp = (const ulonglong2*)(&hbuf[rd][o * 64]);
        unsigned long long ar0 = 0ull, ar1 = 0ull;
        unsigned long long az0 = 0ull, az1 = 0ull;
        unsigned long long an0 = 0ull, an1 = 0ull;
#pragma unroll
        for (int k = 0; k < 16; k++) {
            ulonglong2 hv = hp[k];
            fma2_(ar0, wr_[2*k], hv.x); fma2_(ar1, wr_[2*k+1], hv.y);
            fma2_(az0, wz_[2*k], hv.x); fma2_(az1, wz_[2*k+1], hv.y);
            fma2_(an0, wn_[2*k], hv.x); fma2_(an1, wn_[2*k+1], hv.y);
        }
        float pr = hsum2_(ar0) + hsum2_(ar1);
        float pz = hsum2_(az0) + hsum2_(az1);
        float pn = hsum2_(an0) + hsum2_(an1);

        // ---- butterfly reduce over the 4 column slices (lanes xor 8,16)
#pragma unroll
        for (int d = 8; d < 32; d <<= 1) {
            pr += __shfl_xor_sync(0xffffffffu, pr, d);
            pz += __shfl_xor_sync(0xffffffffu, pz, d);
            pn += __shfl_xor_sync(0xffffffffu, pn, d);
        }

        // ---- gates (all 4 lanes of a j redundantly) ----
        float r    = sigmoid_(g0r + pr + bh_r);
        float z    = sigmoid_(g0z + pz + bh_z);
        float n    = tanh_(g0n + r * (pn + bh_n));
        float hnew = n + z * (hold - n);   // (1-z)*n + z*h
        hold = hnew;

        // ---- gather the 4-group in-octet, send ONE v4 per consumer ----
        float h1 = __shfl_xor_sync(0xffffffffu, hnew, 1);   // j^1
        float h2 = __shfl_xor_sync(0xffffffffu, hnew, 2);   // j^2
        float h3 = __shfl_xor_sync(0xffffffffu, h1,   2);   // j^3
        if ((s + 1) < nsteps && sender) {
            // lane jq%4==0: (hnew,h1,h2,h3) = h[j..j+3]
            st_async_v4(remH[wrb][0], hnew, h1, h2, h3, remMB[wrb][0]);
            st_async_v4(remH[wrb][1], hnew, h1, h2, h3, remMB[wrb][1]);
        }

        // ---- outputs (lane group o==0 only: unique j per store) ----
        if (o == 0) {
            if (enc) {
                if ((s & 127) == 127)
                    outp[(size_t)(s >> 7) * H_ + j] = hnew;
            } else {
                outp[(size_t)(s & 127) * (T_OUT * H_) + (size_t)(s >> 7) * H_ + j] = hnew;
            }
        }

        // rotate gi ring
        g0r = g1r; g0z = g1z; g0n = g1n;
        g1r = nr;  g1z = nz;  g1n = nn;
    }

    // safety: no CTA exits while peers may still address its SMEM
    cluster_arrive_();
    cluster_wait_();
}

// ---------------------------------------------------------------------------
// Launch
// ---------------------------------------------------------------------------
extern "C" void kernel_launch(void* const* d_in, const int* in_sizes, int n_in,
                              void* d_out, int out_size)
{
    const float* x     = (const float*)d_in[0];
    const float* Wih_e = (const float*)d_in[1];
    const float* Whh_e = (const float*)d_in[2];
    const float* bih_e = (const float*)d_in[3];
    const float* bhh_e = (const float*)d_in[4];
    const float* Wih_d = (const float*)d_in[5];
    const float* Whh_d = (const float*)d_in[6];
    const float* bih_d = (const float*)d_in[7];
    const float* bhh_d = (const float*)d_in[8];
    float* out = (float*)d_out;

    gi_kernel<<<ENC_BLOCKS + DEC_BLOCKS, 768>>>(x, Wih_e, bih_e, Wih_d, bih_d);

    cudaLaunchConfig_t cfg = {};
    cfg.gridDim  = dim3(2 * CLUSTER, 1, 1);
    cfg.blockDim = dim3(NTHREADS, 1, 1);
    cfg.dynamicSmemBytes = 0;
    cfg.stream = 0;
    cudaLaunchAttribute attrs[1];
    attrs[0].id = cudaLaunchAttributeClusterDimension;
    attrs[0].val.clusterDim.x = CLUSTER;
    attrs[0].val.clusterDim.y = 1;
    attrs[0].val.clusterDim.z = 1;
    cfg.attrs = attrs;
    cfg.numAttrs = 1;
    cudaLaunchKernelEx(&cfg, scan_kernel, Whh_e, bhh_e, Whh_d, bhh_d, out);
}

// round 12
// speedup vs baseline: 1.3045x; 1.0256x over previous
#include <cuda_runtime.h>
#include <cstdint>

// Problem constants
#define B_       128
#define T_IN     240
#define T_OUT    30
#define D_       128
#define H_       256
#define G3       768              // 3*H
#define STRIDE_  8
#define ENC_STEPS (T_IN * B_)     // 30720
#define DEC_STEPS (T_OUT * B_)    // 3840

// Scratch: precomputed input projections gi = x @ Wih^T + b_ih (+ b_hh for r,z rows)
__device__ float GI_enc[ENC_STEPS * G3];   // ~94.4 MB
__device__ float GI_dec[DEC_STEPS * G3];   // ~11.8 MB

// ---------------------------------------------------------------------------
// Kernel 1: GI GEMM.  GI[s][row] = b_ih[row] + (row<512 ? b_hh[row] : 0)
//                                + sum_d X[s,d] * Wih[row][d]
// (b_hh for the r,z gate rows is folded here; the n-gate's b_hh stays in the
//  scan because it is multiplied by r.)
// ---------------------------------------------------------------------------
#define S_TILE     32
#define ENC_BLOCKS (ENC_STEPS / S_TILE)   // 960
#define DEC_BLOCKS (DEC_STEPS / S_TILE)   // 120

__global__ void __launch_bounds__(768, 1) gi_kernel(
    const float* __restrict__ x,
    const float* __restrict__ Wih_e, const float* __restrict__ bih_e,
    const float* __restrict__ bhh_e,
    const float* __restrict__ Wih_d, const float* __restrict__ bih_d,
    const float* __restrict__ bhh_d)
{
    __shared__ __align__(16) float Xs[S_TILE][D_];   // 16 KB

    bool enc = blockIdx.x < ENC_BLOCKS;
    int  sblk = enc ? blockIdx.x : blockIdx.x - ENC_BLOCKS;
    int  s0   = sblk * S_TILE;
    const float* W   = enc ? Wih_e : Wih_d;
    const float* bih = enc ? bih_e : bih_d;
    const float* bhh = enc ? bhh_e : bhh_d;
    float*       GI  = enc ? GI_enc : GI_dec;
    int tstride = enc ? 1 : STRIDE_;

    int tid = threadIdx.x;

    for (int idx = tid; idx < S_TILE * D_; idx += 768) {
        int i = idx >> 7;
        int k = idx & 127;
        int s = s0 + i;
        int b = s & 127;
        int t = (s >> 7) * tstride;
        Xs[i][k] = x[(size_t)b * (T_IN * D_) + (size_t)t * D_ + k];
    }
    __syncthreads();

    int row = tid;
    const float4* W4 = (const float4*)(W + (size_t)row * D_);

    float acc[S_TILE];
#pragma unroll
    for (int i = 0; i < S_TILE; i++) acc[i] = 0.f;

#pragma unroll 4
    for (int kk = 0; kk < D_ / 4; kk++) {
        float4 w = W4[kk];
#pragma unroll
        for (int i = 0; i < S_TILE; i++) {
            float4 xv = ((const float4*)Xs[i])[kk];
            acc[i] += w.x * xv.x + w.y * xv.y + w.z * xv.z + w.w * xv.w;
        }
    }

    float bv = bih[row] + ((row < 512) ? bhh[row] : 0.f);
#pragma unroll
    for (int i = 0; i < S_TILE; i++)
        GI[(size_t)(s0 + i) * G3 + row] = acc[i] + bv;
}

// ---------------------------------------------------------------------------
// Kernel 2: serial GRU scans.  8-CTA cluster, register-resident W_hh,
// st.async.v4.b32 cross-CTA exchange, 2 ping-pong mbarriers, 128 thr/CTA.
//
// Thread layout:
//   warp w (0..3), lane: o = lane>>3 (column slice 0..3, 64 cols each),
//   jq = lane&7, jloc = w*8 + jq, j = crank*32 + jloc.
// Each thread: rows {j, 256+j, 512+j} x cols [o*64, o*64+64) = 192 weights.
// Reduce: packed pairwise add + hsum, then 2-round shfl butterfly (xor 8,16).
// Gates redundant per lane; hold carried in register; r/z biases pre-folded
// into GI.
// Send: depth-1 gather (h1,h2,h3 = shfl_xor(hnew, 1/2/3)); lanes jq%4==0
// send ONE v4.b32 (global group [j&~3, +4)) to CTA o and CTA o+4.
// Per consumer per step: 8 producers x 8 groups x 16 B = 1024 tx bytes.
// ---------------------------------------------------------------------------
#define CLUSTER  8
#define NTHREADS 128
#define TX_BYTES (H_ * 4)   // 1024

__device__ __forceinline__ uint32_t smem_u32(const void* p) {
    return (uint32_t)__cvta_generic_to_shared(p);
}
__device__ __forceinline__ uint32_t mapa_shared(uint32_t addr, uint32_t rank) {
    uint32_t r;
    asm volatile("mapa.shared::cluster.u32 %0, %1, %2;" : "=r"(r) : "r"(addr), "r"(rank));
    return r;
}
__device__ __forceinline__ void mbar_init_(uint32_t addr, uint32_t count) {
    asm volatile("mbarrier.init.shared.b64 [%0], %1;" :: "r"(addr), "r"(count) : "memory");
}
__device__ __forceinline__ void mbar_arm_(uint32_t addr, uint32_t tx) {
    asm volatile("mbarrier.arrive.expect_tx.shared.b64 _, [%0], %1;"
                 :: "r"(addr), "r"(tx) : "memory");
}
__device__ __forceinline__ void mbar_wait_(uint32_t addr, uint32_t parity) {
    asm volatile(
        "{\n\t"
        ".reg .pred P;\n\t"
        "W_%=:\n\t"
        "mbarrier.try_wait.parity.shared.b64 P, [%0], %1, 0x989680;\n\t"
        "@!P bra W_%=;\n\t"
        "}"
        :: "r"(addr), "r"(parity) : "memory");
}
__device__ __forceinline__ void st_async_v4(uint32_t remote_addr,
                                            float a, float b, float c, float d,
                                            uint32_t remote_mbar) {
    asm volatile(
        "st.async.shared::cluster.mbarrier::complete_tx::bytes.v4.b32 "
        "[%0], {%1, %2, %3, %4}, [%5];"
        :: "r"(remote_addr),
           "r"(__float_as_uint(a)), "r"(__float_as_uint(b)),
           "r"(__float_as_uint(c)), "r"(__float_as_uint(d)),
           "r"(remote_mbar) : "memory");
}
__device__ __forceinline__ void cluster_arrive_() {
    asm volatile("barrier.cluster.arrive.aligned;" ::: "memory");
}
__device__ __forceinline__ void cluster_wait_() {
    asm volatile("barrier.cluster.wait.aligned;" ::: "memory");
}
__device__ __forceinline__ void fma2_(unsigned long long& acc,
                                      unsigned long long a, unsigned long long b) {
    asm("fma.rn.f32x2 %0, %1, %2, %0;" : "+l"(acc) : "l"(a), "l"(b));
}
__device__ __forceinline__ unsigned long long add2_(unsigned long long a,
                                                    unsigned long long b) {
    unsigned long long r;
    asm("add.rn.f32x2 %0, %1, %2;" : "=l"(r) : "l"(a), "l"(b));
    return r;
}
__device__ __forceinline__ float hsum2_(unsigned long long v) {
    float lo, hi;
    asm("mov.b64 {%0, %1}, %2;" : "=f"(lo), "=f"(hi) : "l"(v));
    return lo + hi;
}
__device__ __forceinline__ float sigmoid_(float xv) {
    return __fdividef(1.0f, 1.0f + __expf(-xv));
}
__device__ __forceinline__ float tanh_(float xv) {
    return 1.0f - __fdividef(2.0f, __expf(2.0f * xv) + 1.0f);
}

__global__ void __launch_bounds__(NTHREADS, 1) scan_kernel(
    const float* __restrict__ Whh_e, const float* __restrict__ bhh_e,
    const float* __restrict__ Whh_d, const float* __restrict__ bhh_d,
    float* __restrict__ out)
{
    __shared__ __align__(16) float hbuf[2][H_];
    __shared__ __align__(8) unsigned long long mb[2];   // mb[b] guards hbuf[b]

    bool enc = (blockIdx.x >> 3) == 0;
    uint32_t crank;
    asm("mov.u32 %0, %%cluster_ctarank;" : "=r"(crank));

    const float* Whh = enc ? Whh_e : Whh_d;
    const float* bhh = enc ? bhh_e : bhh_d;
    const float* GI  = enc ? GI_enc : GI_dec;
    int    nsteps = enc ? ENC_STEPS : DEC_STEPS;
    float* outp   = enc ? out : (out + 240 * H_);

    int tid  = threadIdx.x;
    int w    = tid >> 5;
    int lane = tid & 31;
    int o    = lane >> 3;             // column slice (0..3): cols [o*64, o*64+64)
    int jq   = lane & 7;
    int jloc = w * 8 + jq;            // local output index 0..31
    int j    = (int)crank * 32 + jloc;

    // ---- load this thread's 192 weights as 96 packed f32x2 ----
    unsigned long long wr_[32], wz_[32], wn_[32];
    {
        const ulonglong2* Pr = (const ulonglong2*)(Whh + (size_t)j * H_ + o * 64);
        const ulonglong2* Pz = (const ulonglong2*)(Whh + (size_t)(256 + j) * H_ + o * 64);
        const ulonglong2* Pn = (const ulonglong2*)(Whh + (size_t)(512 + j) * H_ + o * 64);
#pragma unroll
        for (int k = 0; k < 16; k++) {
            ulonglong2 vr = Pr[k]; wr_[2*k] = vr.x; wr_[2*k+1] = vr.y;
            ulonglong2 vz = Pz[k]; wz_[2*k] = vz.x; wz_[2*k+1] = vz.y;
            ulonglong2 vn = Pn[k]; wn_[2*k] = vn.x; wn_[2*k+1] = vn.y;
        }
    }

    // only the n-gate hidden bias survives (r,z biases folded into GI)
    float bh_n = bhh[512 + j];

    // remote addresses: senders (jq%4==0) send the GLOBAL 4-group [j&~3, +4)
    // as one v4.b32 to CTA o and CTA o+4.  16-B aligned: (j&~3)*4.
    int jgrp = j & ~3;
    uint32_t remH[2][2], remMB[2][2];
    {
        uint32_t a0 = smem_u32(&hbuf[0][jgrp]);
        uint32_t a1 = smem_u32(&hbuf[1][jgrp]);
        uint32_t m0 = smem_u32(&mb[0]);
        uint32_t m1 = smem_u32(&mb[1]);
        remH[0][0]  = mapa_shared(a0, (uint32_t)o);
        remH[0][1]  = mapa_shared(a0, (uint32_t)(o + 4));
        remH[1][0]  = mapa_shared(a1, (uint32_t)o);
        remH[1][1]  = mapa_shared(a1, (uint32_t)(o + 4));
        remMB[0][0] = mapa_shared(m0, (uint32_t)o);
        remMB[0][1] = mapa_shared(m0, (uint32_t)(o + 4));
        remMB[1][0] = mapa_shared(m1, (uint32_t)o);
        remMB[1][1] = mapa_shared(m1, (uint32_t)(o + 4));
    }
    uint32_t locMB[2] = { smem_u32(&mb[0]), smem_u32(&mb[1]) };

    // init: h0 = 0; barriers init (count=1) and pre-armed for first use
    hbuf[0][tid] = 0.f;
    hbuf[0][tid + 128] = 0.f;
    if (tid == 0) {
        mbar_init_(locMB[0], 1);
        mbar_init_(locMB[1], 1);
        mbar_arm_(locMB[0], TX_BYTES);   // first use: step 2 (h(1))
        mbar_arm_(locMB[1], TX_BYTES);   // first use: step 1 (h(0))
    }
    __syncthreads();
    cluster_arrive_();     // barrier inits visible before any remote st.async
    cluster_wait_();

    // gi prefetch ring, distance 2
    float g0r = __ldg(&GI[j]);
    float g0z = __ldg(&GI[256 + j]);
    float g0n = __ldg(&GI[512 + j]);
    float g1r = 0.f, g1z = 0.f, g1n = 0.f;
    if (nsteps > 1) {
        const float* g = GI + (size_t)G3;
        g1r = __ldg(&g[j]);
        g1z = __ldg(&g[256 + j]);
        g1n = __ldg(&g[512 + j]);
    }

    uint32_t par0 = 0, par1 = 0;   // per-barrier phase parity
    float hold = 0.f;              // h[j], carried in register
    bool sender = ((jq & 3) == 0);

    for (int s = 0; s < nsteps; s++) {
        int rd  = s & 1;          // h(s-1) lives in hbuf[rd], guarded by mb[rd]
        int wrb = rd ^ 1;         // h(s) goes to hbuf[wrb] / mb[wrb]

        // issue gi prefetch for s+2 BEFORE the wait (hides DRAM latency)
        float nr = 0.f, nz = 0.f, nn = 0.f;
        if ((s + 2) < nsteps) {
            const float* g = GI + (size_t)(s + 2) * G3;
            nr = __ldg(&g[j]);
            nz = __ldg(&g[256 + j]);
            nn = __ldg(&g[512 + j]);
        }

        if (s > 0) {
            if (rd) { mbar_wait_(locMB[1], par1); par1 ^= 1; }
            else    { mbar_wait_(locMB[0], par0); par0 ^= 1; }
            // re-arm this barrier for its next use (step s+2), new phase
            if (tid == 0) mbar_arm_(locMB[rd], TX_BYTES);
        }

        // ---- matvec over this thread's 64-col slice (3 rows) ----
        const ulonglong2* hp = (const ulonglong2*)(&hbuf[rd][o * 64]);
        unsigned long long ar0 = 0ull, ar1 = 0ull;
        unsigned long long az0 = 0ull, az1 = 0ull;
        unsigned long long an0 = 0ull, an1 = 0ull;
#pragma unroll
        for (int k = 0; k < 16; k++) {
            ulonglong2 hv = hp[k];
            fma2_(ar0, wr_[2*k], hv.x); fma2_(ar1, wr_[2*k+1], hv.y);
            fma2_(az0, wz_[2*k], hv.x); fma2_(az1, wz_[2*k+1], hv.y);
            fma2_(an0, wn_[2*k], hv.x); fma2_(an1, wn_[2*k+1], hv.y);
        }
        // packed pairwise reduce, then one hsum each
        float pr = hsum2_(add2_(ar0, ar1));
        float pz = hsum2_(add2_(az0, az1));
        float pn = hsum2_(add2_(an0, an1));

        // ---- butterfly reduce over the 4 column slices (lanes xor 8,16)
#pragma unroll
        for (int d = 8; d < 32; d <<= 1) {
            pr += __shfl_xor_sync(0xffffffffu, pr, d);
            pz += __shfl_xor_sync(0xffffffffu, pz, d);
            pn += __shfl_xor_sync(0xffffffffu, pn, d);
        }

        // ---- gates (all 4 lanes of a j redundantly); r/z biases in GI ----
        float r    = sigmoid_(g0r + pr);
        float z    = sigmoid_(g0z + pz);
        float n    = tanh_(g0n + r * (pn + bh_n));
        float hnew = n + z * (hold - n);   // (1-z)*n + z*h
        hold = hnew;

        // ---- depth-1 gather of the 4-group, ONE v4 per consumer ----
        float h1 = __shfl_xor_sync(0xffffffffu, hnew, 1);   // j^1
        float h2 = __shfl_xor_sync(0xffffffffu, hnew, 2);   // j^2
        float h3 = __shfl_xor_sync(0xffffffffu, hnew, 3);   // j^3
        if ((s + 1) < nsteps && sender) {
            // lane jq%4==0: (hnew,h1,h2,h3) = h[j..j+3]
            st_async_v4(remH[wrb][0], hnew, h1, h2, h3, remMB[wrb][0]);
            st_async_v4(remH[wrb][1], hnew, h1, h2, h3, remMB[wrb][1]);
        }

        // ---- outputs (lane group o==0 only: unique j per store) ----
        if (o == 0) {
            if (enc) {
                if ((s & 127) == 127)
                    outp[(size_t)(s >> 7) * H_ + j] = hnew;
            } else {
                outp[(size_t)(s & 127) * (T_OUT * H_) + (size_t)(s >> 7) * H_ + j] = hnew;
            }
        }

        // rotate gi ring
        g0r = g1r; g0z = g1z; g0n = g1n;
        g1r = nr;  g1z = nz;  g1n = nn;
    }

    // safety: no CTA exits while peers may still address its SMEM
    cluster_arrive_();
    cluster_wait_();
}

// ---------------------------------------------------------------------------
// Launch
// ---------------------------------------------------------------------------
extern "C" void kernel_launch(void* const* d_in, const int* in_sizes, int n_in,
                              void* d_out, int out_size)
{
    const float* x     = (const float*)d_in[0];
    const float* Wih_e = (const float*)d_in[1];
    const float* Whh_e = (const float*)d_in[2];
    const float* bih_e = (const float*)d_in[3];
    const float* bhh_e = (const float*)d_in[4];
    const float* Wih_d = (const float*)d_in[5];
    const float* Whh_d = (const float*)d_in[6];
    const float* bih_d = (const float*)d_in[7];
    const float* bhh_d = (const float*)d_in[8];
    float* out = (float*)d_out;

    gi_kernel<<<ENC_BLOCKS + DEC_BLOCKS, 768>>>(x, Wih_e, bih_e, bhh_e,
                                                Wih_d, bih_d, bhh_d);

    cudaLaunchConfig_t cfg = {};
    cfg.gridDim  = dim3(2 * CLUSTER, 1, 1);
    cfg.blockDim = dim3(NTHREADS, 1, 1);
    cfg.dynamicSmemBytes = 0;
    cfg.stream = 0;
    cudaLaunchAttribute attrs[1];
    attrs[0].id = cudaLaunchAttributeClusterDimension;
    attrs[0].val.clusterDim.x = CLUSTER;
    attrs[0].val.clusterDim.y = 1;
    attrs[0].val.clusterDim.z = 1;
    cfg.attrs = attrs;
    cfg.numAttrs = 1;
    cudaLaunchKernelEx(&cfg, scan_kernel, Whh_e, bhh_e, Whh_d, bhh_d, out);
}